// round 3
// baseline (speedup 1.0000x reference)
#include <cuda_runtime.h>

// Problem constants (fixed by reference setup_inputs)
#define B_    2
#define T_    2048
#define C_    1024
#define NHEAD 16
#define HSZ   64
#define W2S   2048   // w2 row stride (block_minus_1)

// Scratch (allocation-free rule: __device__ globals)
__device__ float g_R[B_*T_*C_];   // relu(x @ W1^T + b1), (B*T, C) layout
__device__ float g_V[B_*T_*C_];   // x @ Wv^T + bv
__device__ float g_Y[B_*T_*C_];   // attention output, (B*T, C)

// ---------------------------------------------------------------------------
// C[m,n] = sum_k A[m,k] * W[n,k] + bias[n]  (optional relu)
// A: (M,K) row-major, W: (N,K) row-major. Tiles 128x128x16, 256 threads, 8x8.
// ---------------------------------------------------------------------------
__global__ __launch_bounds__(256, 2)
void gemm_nt(const float* __restrict__ A, const float* __restrict__ W,
             const float* __restrict__ bias, float* __restrict__ out,
             int M, int N, int K, int relu)
{
    __shared__ float As[16][128];
    __shared__ float Ws[16][128];

    const int tid = threadIdx.x;
    const int tx = tid & 15, ty = tid >> 4;
    const int m0 = blockIdx.y * 128, n0 = blockIdx.x * 128;

    const int lr = tid >> 2;          // 0..63
    const int lc = (tid & 3) << 2;    // 0,4,8,12
    const float* Ap = A + (size_t)(m0 + lr) * K + lc;
    const float* Wp = W + (size_t)(n0 + lr) * K + lc;

    float acc[8][8];
    #pragma unroll
    for (int i = 0; i < 8; i++)
        #pragma unroll
        for (int j = 0; j < 8; j++) acc[i][j] = 0.f;

    for (int k0 = 0; k0 < K; k0 += 16) {
        float4 a0 = *(const float4*)(Ap + k0);
        float4 a1 = *(const float4*)(Ap + (size_t)64 * K + k0);
        float4 w0 = *(const float4*)(Wp + k0);
        float4 w1 = *(const float4*)(Wp + (size_t)64 * K + k0);
        __syncthreads();
        As[lc+0][lr]    = a0.x; As[lc+1][lr]    = a0.y; As[lc+2][lr]    = a0.z; As[lc+3][lr]    = a0.w;
        As[lc+0][lr+64] = a1.x; As[lc+1][lr+64] = a1.y; As[lc+2][lr+64] = a1.z; As[lc+3][lr+64] = a1.w;
        Ws[lc+0][lr]    = w0.x; Ws[lc+1][lr]    = w0.y; Ws[lc+2][lr]    = w0.z; Ws[lc+3][lr]    = w0.w;
        Ws[lc+0][lr+64] = w1.x; Ws[lc+1][lr+64] = w1.y; Ws[lc+2][lr+64] = w1.z; Ws[lc+3][lr+64] = w1.w;
        __syncthreads();
        #pragma unroll
        for (int k = 0; k < 16; k++) {
            float a[8], bb[8];
            #pragma unroll
            for (int i = 0; i < 8; i++) a[i] = As[k][ty*8+i];
            #pragma unroll
            for (int j = 0; j < 8; j++) bb[j] = Ws[k][tx*8+j];
            #pragma unroll
            for (int i = 0; i < 8; i++)
                #pragma unroll
                for (int j = 0; j < 8; j++) acc[i][j] += a[i] * bb[j];
        }
    }

    #pragma unroll
    for (int i = 0; i < 8; i++) {
        const int m = m0 + ty*8 + i;
        #pragma unroll
        for (int j = 0; j < 8; j++) {
            const int n = n0 + tx*8 + j;
            float v = acc[i][j] + bias[n];
            if (relu) v = fmaxf(v, 0.f);
            out[(size_t)m * N + n] = v;
        }
    }
}

// ---------------------------------------------------------------------------
// Fused causal synthesizer attention (flash-style):
//   S = R_bh(128 x 64) @ w2[:, jtile](64 x 64) + b2[jtile]
//   causal mask, online softmax, O += P @ V_bh(jtile)(64 x 64)
// Grid: (T/128, NHEAD, B), 256 threads. Thread (tx,ty) owns S rows ty*8..+7,
// S cols tx*4..+3, O cols tx*4..+3. Row reductions via shfl within 16-lane
// groups (same ty). P tile aliases the w2 smem region (85 KB dyn smem total).
// ---------------------------------------------------------------------------
__global__ __launch_bounds__(256, 2)
void synth_attn(const float* __restrict__ R, const float* __restrict__ V,
                const float* __restrict__ w2, const float* __restrict__ b2,
                float* __restrict__ Y)
{
    extern __shared__ float sm[];
    float* R_s  = sm;                    // 128*64
    float* WP_s = sm + 128*64;           // 128*68: w2 tile (first 64 rows) / P tile
    float* V_s  = WP_s + 128*68;         // 64*68

    const int tid = threadIdx.x;
    const int tx = tid & 15, ty = tid >> 4;
    // Reverse t order: heaviest (most causal work) tiles launch first.
    const int t0 = ((int)gridDim.x - 1 - (int)blockIdx.x) * 128;
    const int h  = blockIdx.y, b = blockIdx.z;

    const float* Rbase = R + ((size_t)b * T_ + t0) * C_ + h * HSZ;
    for (int idx = tid; idx < 128 * 16; idx += 256) {
        int r = idx >> 4, c4 = (idx & 15) << 2;
        *(float4*)(R_s + r*64 + c4) = *(const float4*)(Rbase + (size_t)r * C_ + c4);
    }

    float O[8][4];
    float mrow[8], lrow[8];
    #pragma unroll
    for (int i = 0; i < 8; i++) {
        mrow[i] = -1e30f; lrow[i] = 0.f;
        O[i][0] = O[i][1] = O[i][2] = O[i][3] = 0.f;
    }

    const float* Vbase = V + (size_t)b * T_ * C_ + h * HSZ;

    for (int j0 = 0; j0 < t0 + 128; j0 += 64) {
        __syncthreads();  // previous P/V fully consumed (also publishes R_s on iter 0)
        for (int idx = tid; idx < 64 * 16; idx += 256) {
            int d = idx >> 4, c4 = (idx & 15) << 2;
            *(float4*)(WP_s + d*68 + c4) = *(const float4*)(w2 + (size_t)d * W2S + j0 + c4);
        }
        for (int idx = tid; idx < 64 * 16; idx += 256) {
            int r = idx >> 4, c4 = (idx & 15) << 2;
            *(float4*)(V_s + r*68 + c4) = *(const float4*)(Vbase + (size_t)(j0 + r) * C_ + c4);
        }
        __syncthreads();

        // S = R @ w2_tile + b2
        float S[8][4];
        {
            float4 bb = *(const float4*)(b2 + j0 + tx*4);
            #pragma unroll
            for (int i = 0; i < 8; i++) { S[i][0] = bb.x; S[i][1] = bb.y; S[i][2] = bb.z; S[i][3] = bb.w; }
        }
        #pragma unroll 8
        for (int d = 0; d < 64; d++) {
            float4 w4 = *(const float4*)(WP_s + d*68 + tx*4);
            #pragma unroll
            for (int i = 0; i < 8; i++) {
                float a = R_s[(ty*8+i)*64 + d];
                S[i][0] += a * w4.x; S[i][1] += a * w4.y;
                S[i][2] += a * w4.z; S[i][3] += a * w4.w;
            }
        }

        // Causal mask (only diagonal/above-diagonal j-tiles need it)
        if (j0 + 64 > t0) {
            #pragma unroll
            for (int i = 0; i < 8; i++) {
                const int t = t0 + ty*8 + i;
                #pragma unroll
                for (int j = 0; j < 4; j++)
                    if (j0 + tx*4 + j > t) S[i][j] = -1e30f;
            }
        }

        __syncthreads();  // all w2 reads done; WP_s may now hold P

        // Online softmax + write P
        #pragma unroll
        for (int i = 0; i < 8; i++) {
            float rm = fmaxf(fmaxf(S[i][0], S[i][1]), fmaxf(S[i][2], S[i][3]));
            rm = fmaxf(rm, __shfl_xor_sync(0xffffffffu, rm, 1));
            rm = fmaxf(rm, __shfl_xor_sync(0xffffffffu, rm, 2));
            rm = fmaxf(rm, __shfl_xor_sync(0xffffffffu, rm, 4));
            rm = fmaxf(rm, __shfl_xor_sync(0xffffffffu, rm, 8));
            const float mn = fmaxf(mrow[i], rm);
            const float sc = __expf(mrow[i] - mn);
            mrow[i] = mn;
            const float p0 = __expf(S[i][0] - mn);
            const float p1 = __expf(S[i][1] - mn);
            const float p2 = __expf(S[i][2] - mn);
            const float p3 = __expf(S[i][3] - mn);
            float rs = (p0 + p1) + (p2 + p3);
            rs += __shfl_xor_sync(0xffffffffu, rs, 1);
            rs += __shfl_xor_sync(0xffffffffu, rs, 2);
            rs += __shfl_xor_sync(0xffffffffu, rs, 4);
            rs += __shfl_xor_sync(0xffffffffu, rs, 8);
            lrow[i] = lrow[i] * sc + rs;
            O[i][0] *= sc; O[i][1] *= sc; O[i][2] *= sc; O[i][3] *= sc;
            *(float4*)(WP_s + (ty*8+i)*68 + tx*4) = make_float4(p0, p1, p2, p3);
        }
        __syncthreads();

        // O += P @ V_tile
        #pragma unroll 8
        for (int jj = 0; jj < 64; jj++) {
            float4 v4 = *(const float4*)(V_s + jj*68 + tx*4);
            #pragma unroll
            for (int i = 0; i < 8; i++) {
                float p = WP_s[(ty*8+i)*68 + jj];
                O[i][0] += p * v4.x; O[i][1] += p * v4.y;
                O[i][2] += p * v4.z; O[i][3] += p * v4.w;
            }
        }
    }

    float* Ybase = Y + ((size_t)b * T_ + t0) * C_ + h * HSZ;
    #pragma unroll
    for (int i = 0; i < 8; i++) {
        const float inv = 1.f / lrow[i];
        *(float4*)(Ybase + (size_t)(ty*8+i) * C_ + tx*4) =
            make_float4(O[i][0]*inv, O[i][1]*inv, O[i][2]*inv, O[i][3]*inv);
    }
}

// ---------------------------------------------------------------------------
extern "C" void kernel_launch(void* const* d_in, const int* in_sizes, int n_in,
                              void* d_out, int out_size)
{
    const float* x  = (const float*)d_in[0];
    const float* W1 = (const float*)d_in[1];
    const float* b1 = (const float*)d_in[2];
    const float* w2 = (const float*)d_in[3];
    const float* b2 = (const float*)d_in[4];
    const float* Wv = (const float*)d_in[5];
    const float* bv = (const float*)d_in[6];
    const float* Wp = (const float*)d_in[7];
    const float* bp = (const float*)d_in[8];
    float* out = (float*)d_out;

    float *Rp, *Vp, *Yp;
    cudaGetSymbolAddress((void**)&Rp, g_R);
    cudaGetSymbolAddress((void**)&Vp, g_V);
    cudaGetSymbolAddress((void**)&Yp, g_Y);

    const int M = B_ * T_;  // 4096
    dim3 gg(C_ / 128, M / 128);             // (8, 32)

    gemm_nt<<<gg, 256>>>(x, W1, b1, Rp, M, C_, C_, 1);   // R = relu(x W1^T + b1)
    gemm_nt<<<gg, 256>>>(x, Wv, bv, Vp, M, C_, C_, 0);   // V = x Wv^T + bv

    const size_t smem = (size_t)(128*64 + 128*68 + 64*68) * sizeof(float);  // 84992 B
    cudaFuncSetAttribute((const void*)synth_attn,
                         cudaFuncAttributeMaxDynamicSharedMemorySize, (int)smem);
    dim3 ga(T_ / 128, NHEAD, B_);           // (16, 16, 2)
    synth_attn<<<ga, 256, smem>>>(Rp, Vp, w2, b2, Yp);

    gemm_nt<<<gg, 256>>>(Yp, Wp, bp, out, M, C_, C_, 0); // out = Y Wp^T + bp
}

// round 4
// speedup vs baseline: 1.0413x; 1.0413x over previous
#include <cuda_runtime.h>

// Problem constants (fixed by reference setup_inputs)
#define B_    2
#define T_    2048
#define C_    1024
#define NHEAD 16
#define HSZ   64
#define W2S   2048   // w2 row stride (block_minus_1)

typedef unsigned long long u64;

// ---- packed f32x2 helpers (sm_103a FFMA2 path, PTX-only) ----
__device__ __forceinline__ u64 pk2(float lo, float hi) {
    u64 r; asm("mov.b64 %0, {%1, %2};" : "=l"(r) : "f"(lo), "f"(hi)); return r;
}
__device__ __forceinline__ void upk2(u64 v, float &lo, float &hi) {
    asm("mov.b64 {%0, %1}, %2;" : "=f"(lo), "=f"(hi) : "l"(v));
}
__device__ __forceinline__ void fma2(u64 &d, u64 a, u64 b) {
    asm("fma.rn.f32x2 %0, %1, %2, %0;" : "+l"(d) : "l"(a), "l"(b));
}
__device__ __forceinline__ u64 mul2(u64 a, u64 b) {
    u64 r; asm("mul.rn.f32x2 %0, %1, %2;" : "=l"(r) : "l"(a), "l"(b)); return r;
}

// Scratch (allocation-free rule: __device__ globals)
__device__ float g_R[B_*T_*C_];   // relu(x @ W1^T + b1), (B*T, C) layout
__device__ float g_V[B_*T_*C_];   // x @ Wv^T + bv
__device__ float g_Y[B_*T_*C_];   // attention output, (B*T, C)

// ---------------------------------------------------------------------------
// C[m,n] = sum_k A[m,k] * W[n,k] + bias[n]  (optional relu)
// A: (M,K) row-major, W: (N,K) row-major. Tiles 128x128x16, 256 threads, 8x8.
// Inner loop: 4 LDS.128 + 8 dup-packs + 32 FFMA2 per k-step.
// ---------------------------------------------------------------------------
__global__ __launch_bounds__(256, 2)
void gemm_nt(const float* __restrict__ A, const float* __restrict__ W,
             const float* __restrict__ bias, float* __restrict__ out,
             int M, int N, int K, int relu)
{
    __shared__ float As[16][128];
    __shared__ float Ws[16][128];

    const int tid = threadIdx.x;
    const int tx = tid & 15, ty = tid >> 4;
    const int m0 = blockIdx.y * 128, n0 = blockIdx.x * 128;

    const int lr = tid >> 2;          // 0..63
    const int lc = (tid & 3) << 2;    // 0,4,8,12
    const float* Ap = A + (size_t)(m0 + lr) * K + lc;
    const float* Wp = W + (size_t)(n0 + lr) * K + lc;

    u64 acc[8][4];                    // [i-row][j-pair], j packed
    #pragma unroll
    for (int i = 0; i < 8; i++)
        #pragma unroll
        for (int j = 0; j < 4; j++) acc[i][j] = 0ull;

    for (int k0 = 0; k0 < K; k0 += 16) {
        float4 a0 = *(const float4*)(Ap + k0);
        float4 a1 = *(const float4*)(Ap + (size_t)64 * K + k0);
        float4 w0 = *(const float4*)(Wp + k0);
        float4 w1 = *(const float4*)(Wp + (size_t)64 * K + k0);
        __syncthreads();
        As[lc+0][lr]    = a0.x; As[lc+1][lr]    = a0.y; As[lc+2][lr]    = a0.z; As[lc+3][lr]    = a0.w;
        As[lc+0][lr+64] = a1.x; As[lc+1][lr+64] = a1.y; As[lc+2][lr+64] = a1.z; As[lc+3][lr+64] = a1.w;
        Ws[lc+0][lr]    = w0.x; Ws[lc+1][lr]    = w0.y; Ws[lc+2][lr]    = w0.z; Ws[lc+3][lr]    = w0.w;
        Ws[lc+0][lr+64] = w1.x; Ws[lc+1][lr+64] = w1.y; Ws[lc+2][lr+64] = w1.z; Ws[lc+3][lr+64] = w1.w;
        __syncthreads();
        #pragma unroll
        for (int k = 0; k < 16; k++) {
            float4 av0 = *(const float4*)&As[k][ty*8];
            float4 av1 = *(const float4*)&As[k][ty*8 + 4];
            ulonglong2 wp0 = *(const ulonglong2*)&Ws[k][tx*8];      // pairs (j0,j1),(j2,j3)
            ulonglong2 wp1 = *(const ulonglong2*)&Ws[k][tx*8 + 4];  // pairs (j4,j5),(j6,j7)
            float av[8] = {av0.x, av0.y, av0.z, av0.w, av1.x, av1.y, av1.z, av1.w};
            #pragma unroll
            for (int i = 0; i < 8; i++) {
                u64 ad = pk2(av[i], av[i]);
                fma2(acc[i][0], ad, wp0.x);
                fma2(acc[i][1], ad, wp0.y);
                fma2(acc[i][2], ad, wp1.x);
                fma2(acc[i][3], ad, wp1.y);
            }
        }
    }

    const float4 b40 = *(const float4*)(bias + n0 + tx*8);
    const float4 b41 = *(const float4*)(bias + n0 + tx*8 + 4);
    #pragma unroll
    for (int i = 0; i < 8; i++) {
        float c[8];
        upk2(acc[i][0], c[0], c[1]);
        upk2(acc[i][1], c[2], c[3]);
        upk2(acc[i][2], c[4], c[5]);
        upk2(acc[i][3], c[6], c[7]);
        c[0] += b40.x; c[1] += b40.y; c[2] += b40.z; c[3] += b40.w;
        c[4] += b41.x; c[5] += b41.y; c[6] += b41.z; c[7] += b41.w;
        if (relu) {
            #pragma unroll
            for (int j = 0; j < 8; j++) c[j] = fmaxf(c[j], 0.f);
        }
        const int m = m0 + ty*8 + i;
        float* op = out + (size_t)m * N + n0 + tx*8;
        *(float4*)(op)     = make_float4(c[0], c[1], c[2], c[3]);
        *(float4*)(op + 4) = make_float4(c[4], c[5], c[6], c[7]);
    }
}

// ---------------------------------------------------------------------------
// Fused causal synthesizer attention (flash-style), f32x2-packed math.
//   S = R_bh(128 x 64) @ w2[:, jtile](64 x 64) + b2[jtile]
//   causal mask, online softmax, O += P @ V_bh(jtile)
// R is staged TRANSPOSED in smem (Rt[d][row], stride 132) so the S-loop gets
// natural 64-bit row pairs (pack over i). PV packs over j (V pairs natural).
// Grid: (T/128, NHEAD, B), 256 threads. Thread (tx,ty): rows ty*8..+7,
// S/O cols tx*4..+3. Row reductions via shfl within 16-lane groups.
// ---------------------------------------------------------------------------
#define RT_STRIDE 132   // 128 rows + 4 pad, keeps 16B alignment for ull2 loads

__global__ __launch_bounds__(256, 2)
void synth_attn(const float* __restrict__ R, const float* __restrict__ V,
                const float* __restrict__ w2, const float* __restrict__ b2,
                float* __restrict__ Y)
{
    extern __shared__ float sm[];
    float* Rt  = sm;                      // [64][RT_STRIDE]  (transposed R tile)
    float* WP  = sm + 64*RT_STRIDE;       // [128][68]: w2 tile (rows 0..63) / P
    float* V_s = WP + 128*68;             // [64][68]

    const int tid = threadIdx.x;
    const int tx = tid & 15, ty = tid >> 4;
    // Reverse t order: heaviest (most causal work) tiles launch first.
    const int t0 = ((int)gridDim.x - 1 - (int)blockIdx.x) * 128;
    const int h  = blockIdx.y, b = blockIdx.z;

    // Load + transpose R tile: lanes take consecutive rows -> conflict-free STS
    const float* Rbase = R + ((size_t)b * T_ + t0) * C_ + h * HSZ;
    for (int idx = tid; idx < 128 * 16; idx += 256) {
        int r = idx & 127, c4 = (idx >> 7) << 2;
        float4 v = *(const float4*)(Rbase + (size_t)r * C_ + c4);
        Rt[(c4+0)*RT_STRIDE + r] = v.x;
        Rt[(c4+1)*RT_STRIDE + r] = v.y;
        Rt[(c4+2)*RT_STRIDE + r] = v.z;
        Rt[(c4+3)*RT_STRIDE + r] = v.w;
    }

    u64 O2[8][2];                 // [i-row][j-pair], j packed
    float mrow[8], lrow[8];
    #pragma unroll
    for (int i = 0; i < 8; i++) {
        mrow[i] = -1e30f; lrow[i] = 0.f;
        O2[i][0] = 0ull; O2[i][1] = 0ull;
    }

    const float* Vbase = V + (size_t)b * T_ * C_ + h * HSZ;

    for (int j0 = 0; j0 < t0 + 128; j0 += 64) {
        __syncthreads();  // previous P/V fully consumed (also publishes Rt on iter 0)
        for (int idx = tid; idx < 64 * 16; idx += 256) {
            int d = idx >> 4, c4 = (idx & 15) << 2;
            *(float4*)(WP + d*68 + c4) = *(const float4*)(w2 + (size_t)d * W2S + j0 + c4);
        }
        for (int idx = tid; idx < 64 * 16; idx += 256) {
            int r = idx >> 4, c4 = (idx & 15) << 2;
            *(float4*)(V_s + r*68 + c4) = *(const float4*)(Vbase + (size_t)(j0 + r) * C_ + c4);
        }
        __syncthreads();

        // ---- S = R @ w2_tile + b2 ;  S2[i2][j] packs rows (2*i2, 2*i2+1) ----
        u64 S2[4][4];
        {
            float4 bb = *(const float4*)(b2 + j0 + tx*4);
            u64 d0 = pk2(bb.x, bb.x), d1 = pk2(bb.y, bb.y);
            u64 d2 = pk2(bb.z, bb.z), d3 = pk2(bb.w, bb.w);
            #pragma unroll
            for (int i2 = 0; i2 < 4; i2++) {
                S2[i2][0] = d0; S2[i2][1] = d1; S2[i2][2] = d2; S2[i2][3] = d3;
            }
        }
        #pragma unroll 4
        for (int d = 0; d < 64; d++) {
            ulonglong2 rA = *(const ulonglong2*)(Rt + d*RT_STRIDE + ty*8);      // rows 0-3 pairs
            ulonglong2 rB = *(const ulonglong2*)(Rt + d*RT_STRIDE + ty*8 + 4);  // rows 4-7 pairs
            float4 w4 = *(const float4*)(WP + d*68 + tx*4);
            u64 wd0 = pk2(w4.x, w4.x), wd1 = pk2(w4.y, w4.y);
            u64 wd2 = pk2(w4.z, w4.z), wd3 = pk2(w4.w, w4.w);
            fma2(S2[0][0], rA.x, wd0); fma2(S2[0][1], rA.x, wd1);
            fma2(S2[0][2], rA.x, wd2); fma2(S2[0][3], rA.x, wd3);
            fma2(S2[1][0], rA.y, wd0); fma2(S2[1][1], rA.y, wd1);
            fma2(S2[1][2], rA.y, wd2); fma2(S2[1][3], rA.y, wd3);
            fma2(S2[2][0], rB.x, wd0); fma2(S2[2][1], rB.x, wd1);
            fma2(S2[2][2], rB.x, wd2); fma2(S2[2][3], rB.x, wd3);
            fma2(S2[3][0], rB.y, wd0); fma2(S2[3][1], rB.y, wd1);
            fma2(S2[3][2], rB.y, wd2); fma2(S2[3][3], rB.y, wd3);
        }

        __syncthreads();  // all w2 reads done; WP may now hold P

        // ---- mask + online softmax + write P ----
        float scrow[8];
        #pragma unroll
        for (int i2 = 0; i2 < 4; i2++) {
            float s[2][4];
            upk2(S2[i2][0], s[0][0], s[1][0]);
            upk2(S2[i2][1], s[0][1], s[1][1]);
            upk2(S2[i2][2], s[0][2], s[1][2]);
            upk2(S2[i2][3], s[0][3], s[1][3]);
            #pragma unroll
            for (int hh = 0; hh < 2; hh++) {
                const int i = 2*i2 + hh;
                const int t = t0 + ty*8 + i;
                if (j0 + 64 > t0) {
                    #pragma unroll
                    for (int j = 0; j < 4; j++)
                        if (j0 + tx*4 + j > t) s[hh][j] = -1e30f;
                }
                float rm = fmaxf(fmaxf(s[hh][0], s[hh][1]), fmaxf(s[hh][2], s[hh][3]));
                rm = fmaxf(rm, __shfl_xor_sync(0xffffffffu, rm, 1));
                rm = fmaxf(rm, __shfl_xor_sync(0xffffffffu, rm, 2));
                rm = fmaxf(rm, __shfl_xor_sync(0xffffffffu, rm, 4));
                rm = fmaxf(rm, __shfl_xor_sync(0xffffffffu, rm, 8));
                const float mn = fmaxf(mrow[i], rm);
                const float sc = __expf(mrow[i] - mn);
                mrow[i] = mn;
                const float p0 = __expf(s[hh][0] - mn);
                const float p1 = __expf(s[hh][1] - mn);
                const float p2 = __expf(s[hh][2] - mn);
                const float p3 = __expf(s[hh][3] - mn);
                float rs = (p0 + p1) + (p2 + p3);
                rs += __shfl_xor_sync(0xffffffffu, rs, 1);
                rs += __shfl_xor_sync(0xffffffffu, rs, 2);
                rs += __shfl_xor_sync(0xffffffffu, rs, 4);
                rs += __shfl_xor_sync(0xffffffffu, rs, 8);
                lrow[i] = lrow[i] * sc + rs;
                scrow[i] = sc;
                *(float4*)(WP + (ty*8+i)*68 + tx*4) = make_float4(p0, p1, p2, p3);
            }
        }
        #pragma unroll
        for (int i = 0; i < 8; i++) {
            u64 sp = pk2(scrow[i], scrow[i]);
            O2[i][0] = mul2(O2[i][0], sp);
            O2[i][1] = mul2(O2[i][1], sp);
        }
        __syncthreads();

        // ---- O += P @ V_tile  (pack over j: V pairs natural, P broadcast dup) ----
        #pragma unroll 4
        for (int jj = 0; jj < 64; jj++) {
            ulonglong2 vv = *(const ulonglong2*)(V_s + jj*68 + tx*4);
            const float* prow = WP + jj;
            #pragma unroll
            for (int i = 0; i < 8; i++) {
                float p = prow[(ty*8+i)*68];
                u64 pd = pk2(p, p);
                fma2(O2[i][0], pd, vv.x);
                fma2(O2[i][1], pd, vv.y);
            }
        }
    }

    float* Ybase = Y + ((size_t)b * T_ + t0) * C_ + h * HSZ;
    #pragma unroll
    for (int i = 0; i < 8; i++) {
        float o0, o1, o2, o3;
        upk2(O2[i][0], o0, o1);
        upk2(O2[i][1], o2, o3);
        const float inv = 1.f / lrow[i];
        *(float4*)(Ybase + (size_t)(ty*8+i) * C_ + tx*4) =
            make_float4(o0*inv, o1*inv, o2*inv, o3*inv);
    }
}

// ---------------------------------------------------------------------------
extern "C" void kernel_launch(void* const* d_in, const int* in_sizes, int n_in,
                              void* d_out, int out_size)
{
    const float* x  = (const float*)d_in[0];
    const float* W1 = (const float*)d_in[1];
    const float* b1 = (const float*)d_in[2];
    const float* w2 = (const float*)d_in[3];
    const float* b2 = (const float*)d_in[4];
    const float* Wv = (const float*)d_in[5];
    const float* bv = (const float*)d_in[6];
    const float* Wp = (const float*)d_in[7];
    const float* bp = (const float*)d_in[8];
    float* out = (float*)d_out;

    float *Rp, *Vp, *Yp;
    cudaGetSymbolAddress((void**)&Rp, g_R);
    cudaGetSymbolAddress((void**)&Vp, g_V);
    cudaGetSymbolAddress((void**)&Yp, g_Y);

    const int M = B_ * T_;  // 4096
    dim3 gg(C_ / 128, M / 128);             // (8, 32)

    gemm_nt<<<gg, 256>>>(x, W1, b1, Rp, M, C_, C_, 1);   // R = relu(x W1^T + b1)
    gemm_nt<<<gg, 256>>>(x, Wv, bv, Vp, M, C_, C_, 0);   // V = x Wv^T + bv

    const size_t smem = (size_t)(64*RT_STRIDE + 128*68 + 64*68) * sizeof(float);  // 86016 B
    cudaFuncSetAttribute((const void*)synth_attn,
                         cudaFuncAttributeMaxDynamicSharedMemorySize, (int)smem);
    dim3 ga(T_ / 128, NHEAD, B_);           // (16, 16, 2)
    synth_attn<<<ga, 256, smem>>>(Rp, Vp, w2, b2, Yp);

    gemm_nt<<<gg, 256>>>(Yp, Wp, bp, out, M, C_, C_, 0); // out = Y Wp^T + bp
}

// round 8
// speedup vs baseline: 1.0630x; 1.0208x over previous
#include <cuda_runtime.h>

// Problem constants (fixed by reference setup_inputs)
#define B_    2
#define T_    2048
#define C_    1024
#define NHEAD 16
#define HSZ   64
#define W2S   2048   // w2 row stride (block_minus_1)

typedef unsigned long long u64;

// ---- packed f32x2 helpers (sm_103a, PTX-only; issue-slot saver) ----
__device__ __forceinline__ u64 pk2(float lo, float hi) {
    u64 r; asm("mov.b64 %0, {%1, %2};" : "=l"(r) : "f"(lo), "f"(hi)); return r;
}
__device__ __forceinline__ void upk2(u64 v, float &lo, float &hi) {
    asm("mov.b64 {%0, %1}, %2;" : "=f"(lo), "=f"(hi) : "l"(v));
}
__device__ __forceinline__ void fma2(u64 &d, u64 a, u64 b) {
    asm("fma.rn.f32x2 %0, %1, %2, %0;" : "+l"(d) : "l"(a), "l"(b));
}
__device__ __forceinline__ u64 mul2(u64 a, u64 b) {
    u64 r; asm("mul.rn.f32x2 %0, %1, %2;" : "=l"(r) : "l"(a), "l"(b)); return r;
}

// Scratch (allocation-free rule: __device__ globals)
__device__ float g_R[B_*T_*C_];   // relu(x @ W1^T + b1), (B*T, C) layout
__device__ float g_V[B_*T_*C_];   // x @ Wv^T + bv
__device__ float g_Y[B_*T_*C_];   // attention output, (B*T, C)

// ---------------------------------------------------------------------------
// C[m,n] = sum_k A[m,k] * W[n,k] + bias[n]  (optional relu)
// A: (M,K) row-major, W: (N,K) row-major. Tiles 128x128x16, 256 threads, 8x8.
// Software-pipelined: next k-tile's LDGs prefetched to registers during the
// compute phase; the inter-barrier window is pure STS.
// ---------------------------------------------------------------------------
__global__ __launch_bounds__(256, 2)
void gemm_nt(const float* __restrict__ A, const float* __restrict__ W,
             const float* __restrict__ bias, float* __restrict__ out,
             int M, int N, int K, int relu)
{
    __shared__ float As[16][128];
    __shared__ float Ws[16][128];

    const int tid = threadIdx.x;
    const int tx = tid & 15, ty = tid >> 4;
    const int m0 = blockIdx.y * 128, n0 = blockIdx.x * 128;

    const int lr = tid >> 2;          // 0..63
    const int lc = (tid & 3) << 2;    // 0,4,8,12
    const float* Ap = A + (size_t)(m0 + lr) * K + lc;
    const float* Wp = W + (size_t)(n0 + lr) * K + lc;

    u64 acc[8][4];                    // [i-row][j-pair], j packed
    #pragma unroll
    for (int i = 0; i < 8; i++)
        #pragma unroll
        for (int j = 0; j < 4; j++) acc[i][j] = 0ull;

    // Prefetch k-tile 0
    float4 a0 = *(const float4*)(Ap);
    float4 a1 = *(const float4*)(Ap + (size_t)64 * K);
    float4 w0 = *(const float4*)(Wp);
    float4 w1 = *(const float4*)(Wp + (size_t)64 * K);

    for (int k0 = 0; k0 < K; k0 += 16) {
        __syncthreads();              // previous tile's compute done
        As[lc+0][lr]    = a0.x; As[lc+1][lr]    = a0.y; As[lc+2][lr]    = a0.z; As[lc+3][lr]    = a0.w;
        As[lc+0][lr+64] = a1.x; As[lc+1][lr+64] = a1.y; As[lc+2][lr+64] = a1.z; As[lc+3][lr+64] = a1.w;
        Ws[lc+0][lr]    = w0.x; Ws[lc+1][lr]    = w0.y; Ws[lc+2][lr]    = w0.z; Ws[lc+3][lr]    = w0.w;
        Ws[lc+0][lr+64] = w1.x; Ws[lc+1][lr+64] = w1.y; Ws[lc+2][lr+64] = w1.z; Ws[lc+3][lr+64] = w1.w;
        __syncthreads();
        if (k0 + 16 < K) {            // prefetch next tile; latency hidden by compute below
            a0 = *(const float4*)(Ap + k0 + 16);
            a1 = *(const float4*)(Ap + (size_t)64 * K + k0 + 16);
            w0 = *(const float4*)(Wp + k0 + 16);
            w1 = *(const float4*)(Wp + (size_t)64 * K + k0 + 16);
        }
        #pragma unroll
        for (int k = 0; k < 16; k++) {
            float4 av0 = *(const float4*)&As[k][ty*8];
            float4 av1 = *(const float4*)&As[k][ty*8 + 4];
            ulonglong2 wp0 = *(const ulonglong2*)&Ws[k][tx*8];      // pairs (j0,j1),(j2,j3)
            ulonglong2 wp1 = *(const ulonglong2*)&Ws[k][tx*8 + 4];  // pairs (j4,j5),(j6,j7)
            float av[8] = {av0.x, av0.y, av0.z, av0.w, av1.x, av1.y, av1.z, av1.w};
            #pragma unroll
            for (int i = 0; i < 8; i++) {
                u64 ad = pk2(av[i], av[i]);
                fma2(acc[i][0], ad, wp0.x);
                fma2(acc[i][1], ad, wp0.y);
                fma2(acc[i][2], ad, wp1.x);
                fma2(acc[i][3], ad, wp1.y);
            }
        }
    }

    const float4 b40 = *(const float4*)(bias + n0 + tx*8);
    const float4 b41 = *(const float4*)(bias + n0 + tx*8 + 4);
    #pragma unroll
    for (int i = 0; i < 8; i++) {
        float c[8];
        upk2(acc[i][0], c[0], c[1]);
        upk2(acc[i][1], c[2], c[3]);
        upk2(acc[i][2], c[4], c[5]);
        upk2(acc[i][3], c[6], c[7]);
        c[0] += b40.x; c[1] += b40.y; c[2] += b40.z; c[3] += b40.w;
        c[4] += b41.x; c[5] += b41.y; c[6] += b41.z; c[7] += b41.w;
        if (relu) {
            #pragma unroll
            for (int j = 0; j < 8; j++) c[j] = fmaxf(c[j], 0.f);
        }
        const int m = m0 + ty*8 + i;
        float* op = out + (size_t)m * N + n0 + tx*8;
        *(float4*)(op)     = make_float4(c[0], c[1], c[2], c[3]);
        *(float4*)(op + 4) = make_float4(c[4], c[5], c[6], c[7]);
    }
}

// ---------------------------------------------------------------------------
// Fused causal synthesizer attention (flash-style), f32x2-packed math,
// software-pipelined tile loads (w2/V of tile j+1 prefetched to registers
// during tile j's compute).
//   S = R_bh(128 x 64) @ w2[:, jtile](64 x 64) + b2[jtile]
//   causal mask, online softmax, O += P @ V_bh(jtile)
// R staged TRANSPOSED in smem (Rt[d][row]) -> natural 64-bit row pairs for
// the S-loop. P aliases the w2 smem tile. Grid: (T/128, NHEAD, B), 256 thr.
// ---------------------------------------------------------------------------
#define RT_STRIDE 132   // 128 rows + 4 pad, keeps 16B alignment for ull2 loads

__global__ __launch_bounds__(256, 2)
void synth_attn(const float* __restrict__ R, const float* __restrict__ V,
                const float* __restrict__ w2, const float* __restrict__ b2,
                float* __restrict__ Y)
{
    extern __shared__ float sm[];
    float* Rt  = sm;                      // [64][RT_STRIDE]  (transposed R tile)
    float* WP  = sm + 64*RT_STRIDE;       // [128][68]: w2 tile (rows 0..63) / P
    float* V_s = WP + 128*68;             // [64][68]

    const int tid = threadIdx.x;
    const int tx = tid & 15, ty = tid >> 4;
    // Reverse t order: heaviest (most causal work) tiles launch first.
    const int t0 = ((int)gridDim.x - 1 - (int)blockIdx.x) * 128;
    const int h  = blockIdx.y, b = blockIdx.z;

    // Load + transpose R tile: lanes take consecutive rows -> conflict-free STS
    const float* Rbase = R + ((size_t)b * T_ + t0) * C_ + h * HSZ;
    for (int idx = tid; idx < 128 * 16; idx += 256) {
        int r = idx & 127, c4 = (idx >> 7) << 2;
        float4 v = *(const float4*)(Rbase + (size_t)r * C_ + c4);
        Rt[(c4+0)*RT_STRIDE + r] = v.x;
        Rt[(c4+1)*RT_STRIDE + r] = v.y;
        Rt[(c4+2)*RT_STRIDE + r] = v.z;
        Rt[(c4+3)*RT_STRIDE + r] = v.w;
    }

    u64 O2[8][2];                 // [i-row][j-pair], j packed
    float mrow[8], lrow[8];
    #pragma unroll
    for (int i = 0; i < 8; i++) {
        mrow[i] = -1e30f; lrow[i] = 0.f;
        O2[i][0] = 0ull; O2[i][1] = 0ull;
    }

    const float* Vbase = V + (size_t)b * T_ * C_ + h * HSZ;

    // Per-thread tile-load mapping: idx = tid + p*256; d = idx>>4, c4 = (idx&15)*4
    const int pd  = tid >> 4;            // row/d base (0..15), +16 per p
    const int pc4 = (tid & 15) << 2;     // col (0,4,...,60)

    // Prefetch tile j0 = 0
    float4 pw[4], pv[4];
    #pragma unroll
    for (int p = 0; p < 4; p++) {
        const int d = pd + p*16;
        pw[p] = *(const float4*)(w2 + (size_t)d * W2S + 0 + pc4);
        pv[p] = *(const float4*)(Vbase + (size_t)(0 + d) * C_ + pc4);
    }

    const int jend = t0 + 128;
    for (int j0 = 0; j0 < jend; j0 += 64) {
        __syncthreads();  // previous P/V fully consumed (also publishes Rt on iter 0)
        #pragma unroll
        for (int p = 0; p < 4; p++) {
            const int d = pd + p*16;
            *(float4*)(WP  + d*68 + pc4) = pw[p];
            *(float4*)(V_s + d*68 + pc4) = pv[p];
        }
        __syncthreads();

        // Prefetch next tile; latency hidden by S/softmax/PV compute below
        if (j0 + 64 < jend) {
            #pragma unroll
            for (int p = 0; p < 4; p++) {
                const int d = pd + p*16;
                pw[p] = *(const float4*)(w2 + (size_t)d * W2S + (j0 + 64) + pc4);
                pv[p] = *(const float4*)(Vbase + (size_t)(j0 + 64 + d) * C_ + pc4);
            }
        }

        // ---- S = R @ w2_tile + b2 ;  S2[i2][j] packs rows (2*i2, 2*i2+1) ----
        u64 S2[4][4];
        {
            float4 bb = *(const float4*)(b2 + j0 + tx*4);
            u64 d0 = pk2(bb.x, bb.x), d1 = pk2(bb.y, bb.y);
            u64 d2 = pk2(bb.z, bb.z), d3 = pk2(bb.w, bb.w);
            #pragma unroll
            for (int i2 = 0; i2 < 4; i2++) {
                S2[i2][0] = d0; S2[i2][1] = d1; S2[i2][2] = d2; S2[i2][3] = d3;
            }
        }
        #pragma unroll 4
        for (int d = 0; d < 64; d++) {
            ulonglong2 rA = *(const ulonglong2*)(Rt + d*RT_STRIDE + ty*8);      // rows 0-3 pairs
            ulonglong2 rB = *(const ulonglong2*)(Rt + d*RT_STRIDE + ty*8 + 4);  // rows 4-7 pairs
            float4 w4 = *(const float4*)(WP + d*68 + tx*4);
            u64 wd0 = pk2(w4.x, w4.x), wd1 = pk2(w4.y, w4.y);
            u64 wd2 = pk2(w4.z, w4.z), wd3 = pk2(w4.w, w4.w);
            fma2(S2[0][0], rA.x, wd0); fma2(S2[0][1], rA.x, wd1);
            fma2(S2[0][2], rA.x, wd2); fma2(S2[0][3], rA.x, wd3);
            fma2(S2[1][0], rA.y, wd0); fma2(S2[1][1], rA.y, wd1);
            fma2(S2[1][2], rA.y, wd2); fma2(S2[1][3], rA.y, wd3);
            fma2(S2[2][0], rB.x, wd0); fma2(S2[2][1], rB.x, wd1);
            fma2(S2[2][2], rB.x, wd2); fma2(S2[2][3], rB.x, wd3);
            fma2(S2[3][0], rB.y, wd0); fma2(S2[3][1], rB.y, wd1);
            fma2(S2[3][2], rB.y, wd2); fma2(S2[3][3], rB.y, wd3);
        }

        __syncthreads();  // all w2 reads done; WP may now hold P

        // ---- mask + online softmax + write P ----
        float scrow[8];
        #pragma unroll
        for (int i2 = 0; i2 < 4; i2++) {
            float s[2][4];
            upk2(S2[i2][0], s[0][0], s[1][0]);
            upk2(S2[i2][1], s[0][1], s[1][1]);
            upk2(S2[i2][2], s[0][2], s[1][2]);
            upk2(S2[i2][3], s[0][3], s[1][3]);
            #pragma unroll
            for (int hh = 0; hh < 2; hh++) {
                const int i = 2*i2 + hh;
                const int t = t0 + ty*8 + i;
                if (j0 + 64 > t0) {
                    #pragma unroll
                    for (int j = 0; j < 4; j++)
                        if (j0 + tx*4 + j > t) s[hh][j] = -1e30f;
                }
                float rm = fmaxf(fmaxf(s[hh][0], s[hh][1]), fmaxf(s[hh][2], s[hh][3]));
                rm = fmaxf(rm, __shfl_xor_sync(0xffffffffu, rm, 1));
                rm = fmaxf(rm, __shfl_xor_sync(0xffffffffu, rm, 2));
                rm = fmaxf(rm, __shfl_xor_sync(0xffffffffu, rm, 4));
                rm = fmaxf(rm, __shfl_xor_sync(0xffffffffu, rm, 8));
                const float mn = fmaxf(mrow[i], rm);
                const float sc = __expf(mrow[i] - mn);
                mrow[i] = mn;
                const float p0 = __expf(s[hh][0] - mn);
                const float p1 = __expf(s[hh][1] - mn);
                const float p2 = __expf(s[hh][2] - mn);
                const float p3 = __expf(s[hh][3] - mn);
                float rs = (p0 + p1) + (p2 + p3);
                rs += __shfl_xor_sync(0xffffffffu, rs, 1);
                rs += __shfl_xor_sync(0xffffffffu, rs, 2);
                rs += __shfl_xor_sync(0xffffffffu, rs, 4);
                rs += __shfl_xor_sync(0xffffffffu, rs, 8);
                lrow[i] = lrow[i] * sc + rs;
                scrow[i] = sc;
                *(float4*)(WP + (ty*8+i)*68 + tx*4) = make_float4(p0, p1, p2, p3);
            }
        }
        #pragma unroll
        for (int i = 0; i < 8; i++) {
            u64 sp = pk2(scrow[i], scrow[i]);
            O2[i][0] = mul2(O2[i][0], sp);
            O2[i][1] = mul2(O2[i][1], sp);
        }
        __syncthreads();

        // ---- O += P @ V_tile  (pack over j: V pairs natural, P broadcast dup) ----
        #pragma unroll 4
        for (int jj = 0; jj < 64; jj++) {
            ulonglong2 vv = *(const ulonglong2*)(V_s + jj*68 + tx*4);
            const float* prow = WP + jj;
            #pragma unroll
            for (int i = 0; i < 8; i++) {
                float p = prow[(ty*8+i)*68];
                u64 pd2 = pk2(p, p);
                fma2(O2[i][0], pd2, vv.x);
                fma2(O2[i][1], pd2, vv.y);
            }
        }
    }

    float* Ybase = Y + ((size_t)b * T_ + t0) * C_ + h * HSZ;
    #pragma unroll
    for (int i = 0; i < 8; i++) {
        float o0, o1, o2, o3;
        upk2(O2[i][0], o0, o1);
        upk2(O2[i][1], o2, o3);
        const float inv = 1.f / lrow[i];
        *(float4*)(Ybase + (size_t)(ty*8+i) * C_ + tx*4) =
            make_float4(o0*inv, o1*inv, o2*inv, o3*inv);
    }
}

// ---------------------------------------------------------------------------
extern "C" void kernel_launch(void* const* d_in, const int* in_sizes, int n_in,
                              void* d_out, int out_size)
{
    const float* x  = (const float*)d_in[0];
    const float* W1 = (const float*)d_in[1];
    const float* b1 = (const float*)d_in[2];
    const float* w2 = (const float*)d_in[3];
    const float* b2 = (const float*)d_in[4];
    const float* Wv = (const float*)d_in[5];
    const float* bv = (const float*)d_in[6];
    const float* Wp = (const float*)d_in[7];
    const float* bp = (const float*)d_in[8];
    float* out = (float*)d_out;

    float *Rp, *Vp, *Yp;
    cudaGetSymbolAddress((void**)&Rp, g_R);
    cudaGetSymbolAddress((void**)&Vp, g_V);
    cudaGetSymbolAddress((void**)&Yp, g_Y);

    const int M = B_ * T_;  // 4096
    dim3 gg(C_ / 128, M / 128);             // (8, 32)

    gemm_nt<<<gg, 256>>>(x, W1, b1, Rp, M, C_, C_, 1);   // R = relu(x W1^T + b1)
    gemm_nt<<<gg, 256>>>(x, Wv, bv, Vp, M, C_, C_, 0);   // V = x Wv^T + bv

    const size_t smem = (size_t)(64*RT_STRIDE + 128*68 + 64*68) * sizeof(float);  // 86016 B
    cudaFuncSetAttribute((const void*)synth_attn,
                         cudaFuncAttributeMaxDynamicSharedMemorySize, (int)smem);
    dim3 ga(T_ / 128, NHEAD, B_);           // (16, 16, 2)
    synth_attn<<<ga, 256, smem>>>(Rp, Vp, w2, b2, Yp);

    gemm_nt<<<gg, 256>>>(Yp, Wp, bp, out, M, C_, C_, 0); // out = Y Wp^T + bp
}